// round 15
// baseline (speedup 1.0000x reference)
#include <cuda_runtime.h>
#include <cuda_bf16.h>

// GRU scan: B=2048 sequences, T=2048 steps, D=3 input, H=32 hidden.
// out[b, t] = h[0] after step t.
//
// R15 = R12 (occ-4, 1 batch/warp, 2048 warps, k-pair-packed Whh) with 28
// MORE registers of demand moved to CTA-shared tables to finally clear the
// 128-reg occ-4 cap (R5/R11/R12 all spilled; each removed chunk paid):
//  - a-gate weights k[16..31]: 8 u64 -> smem table, 4 lane-strided
//    LDS.128/step (16 wf -- half of R9's fatal 32 wf/step budget).
//  - input-gate weights + biases: 12 scalars -> smem, 12 lane-strided
//    LDS.32/step.
//  - both tables DUPLICATED per parity slot and indexed by (t&1) so the
//    addresses are loop-variant: ptxas cannot hoist them back into regs
//    and recreate the spill.
//  - accumulators seeded with ig in the lo half; double-buffered smem h
//    broadcast, one syncwarp/step; EX2/RCP activations (tanh.approx is an
//    fma-pipe polyfill on sm_103a -- regressed in R7).
// True demand ~106 regs -> expect regs < 128 reported (success signal).

#define T_DIM 2048
#define B_DIM 2048

typedef unsigned long long u64;

__device__ __forceinline__ u64 fma2(u64 a, u64 b, u64 c) {
    u64 d;
    asm("fma.rn.f32x2 %0, %1, %2, %3;" : "=l"(d) : "l"(a), "l"(b), "l"(c));
    return d;
}

__device__ __forceinline__ u64 pack2(float a, float b) {
    u64 d;
    asm("mov.b64 %0, {%1, %2};" : "=l"(d) : "f"(a), "f"(b));
    return d;
}

__device__ __forceinline__ float foldadd(u64 p) {
    float lo, hi;
    asm("mov.b64 {%0, %1}, %2;" : "=f"(lo), "=f"(hi) : "l"(p));
    return lo + hi;
}

__device__ __forceinline__ float sigm_f(float x) {
    return __fdividef(1.0f, 1.0f + __expf(-x));
}

__device__ __forceinline__ float tanh_f(float x) {
    return 1.0f - __fdividef(2.0f, __expf(2.0f * x) + 1.0f);
}

__global__ void __launch_bounds__(128, 4)
gru_scan_kernel(const float* __restrict__ inp,      // [B, T, 3]
                const float* __restrict__ wih,      // [96, 3]
                const float* __restrict__ whh,      // [96, 32]
                const float* __restrict__ bias,     // [96]
                const float* __restrict__ bias_n,   // [32]
                float* __restrict__ out)            // [B, T]
{
    const int lane = threadIdx.x & 31;
    const int warp = threadIdx.x >> 5;
    const int b    = blockIdx.x * 4 + warp;

    // per-warp double-buffered h slab; 16B-aligned for LDS.128 broadcast
    __shared__ __align__(16) float hbuf[4][2][32];
    // a-gate weights k[16..31] as k-pair u64s, slot-duplicated (anti-hoist):
    // wa_s[slot][i][lane] = (wa_pair[8+2i], wa_pair[9+2i]) for unit `lane`.
    __shared__ __align__(16) ulonglong2 wa_s[2][4][32];
    // input-gate params, slot-duplicated, lane-strided scalar layout:
    // igw[slot][p][lane], p = 4*gate + {w0,w1,w2,bias}.
    __shared__ float igw[2][12][32];

    {
        const int tid = threadIdx.x;
        if (tid < 96) {
            const int g = tid >> 5;        // gate 0=r, 1=z, 2=a
            const int l = tid & 31;
            const int row = g * 32 + l;
            float bb = bias[row];
            if (g == 2) bb += bias_n[l];   // fold bias_n into a-gate bias
            igw[0][4 * g + 0][l] = wih[row * 3 + 0];
            igw[0][4 * g + 1][l] = wih[row * 3 + 1];
            igw[0][4 * g + 2][l] = wih[row * 3 + 2];
            igw[0][4 * g + 3][l] = bb;
            igw[1][4 * g + 0][l] = wih[row * 3 + 0];
            igw[1][4 * g + 1][l] = wih[row * 3 + 1];
            igw[1][4 * g + 2][l] = wih[row * 3 + 2];
            igw[1][4 * g + 3][l] = bb;
        }
        if (warp == 0) {
            const u64* arow =
                reinterpret_cast<const u64*>(whh + (size_t)(64 + lane) * 32);
#pragma unroll
            for (int i = 0; i < 4; ++i) {
                ulonglong2 v;
                v.x = arow[8 + 2 * i];
                v.y = arow[9 + 2 * i];
                wa_s[0][i][lane] = v;
                wa_s[1][i][lane] = v;
            }
        }
    }

    // --- register-resident weights: wr, wz full; wa only k[0..15] ---
    u64 wr[16], wz[16], wa[8];          // 40 u64 = 80 regs
    {
        const u64* r0 = reinterpret_cast<const u64*>(whh + (size_t)(lane) * 32);
        const u64* r1 = reinterpret_cast<const u64*>(whh + (size_t)(32 + lane) * 32);
        const u64* r2 = reinterpret_cast<const u64*>(whh + (size_t)(64 + lane) * 32);
#pragma unroll
        for (int i = 0; i < 16; ++i) { wr[i] = r0[i]; wz[i] = r1[i]; }
#pragma unroll
        for (int i = 0; i < 8; ++i)  { wa[i] = r2[i]; }
    }

    const float* xp = inp + (size_t)b * T_DIM * 3;
    float*       op = out + (size_t)b * T_DIM;

    float h = 0.0f;

    __syncthreads();   // tables ready

    for (int t = 0; t < T_DIM; ++t) {
        const int slot = t & 1;

        // x loaded in-loop (L1-resident line ~10 steps; occ-4 hides misses)
        const float* xt = xp + (size_t)t * 3;
        float x0 = __ldg(xt + 0), x1 = __ldg(xt + 1), x2 = __ldg(xt + 2);

        // input gates from the slot-indexed scalar table (12 LDS.32)
        const float* gp = &igw[slot][0][lane];
        float ir = fmaf(gp[2 * 32], x2,
                   fmaf(gp[1 * 32], x1, fmaf(gp[0 * 32], x0, gp[3 * 32])));
        float iz = fmaf(gp[6 * 32], x2,
                   fmaf(gp[5 * 32], x1, fmaf(gp[4 * 32], x0, gp[7 * 32])));
        float ia = fmaf(gp[10 * 32], x2,
                   fmaf(gp[9 * 32], x1, fmaf(gp[8 * 32], x0, gp[11 * 32])));

        // publish h_j; double-buffered slot => one syncwarp per step
        hbuf[warp][slot][lane] = h;
        __syncwarp();

        // matvec, accumulators seeded with ig in the lo half
        u64 ar = pack2(ir, 0.0f);
        u64 az = pack2(iz, 0.0f);
        u64 aa = pack2(ia, 0.0f);
        const ulonglong2* hp =
            reinterpret_cast<const ulonglong2*>(&hbuf[warp][slot][0]);
#pragma unroll
        for (int i = 0; i < 4; ++i) {    // k pairs 0..7 (wa from registers)
            ulonglong2 hv = hp[i];
            ar = fma2(wr[2 * i],     hv.x, ar);
            az = fma2(wz[2 * i],     hv.x, az);
            aa = fma2(wa[2 * i],     hv.x, aa);
            ar = fma2(wr[2 * i + 1], hv.y, ar);
            az = fma2(wz[2 * i + 1], hv.y, az);
            aa = fma2(wa[2 * i + 1], hv.y, aa);
        }
#pragma unroll
        for (int i = 4; i < 8; ++i) {    // k pairs 8..15 (wa from smem table)
            ulonglong2 hv = hp[i];
            ulonglong2 wv = wa_s[slot][i - 4][lane];   // lane-strided LDS.128
            ar = fma2(wr[2 * i],     hv.x, ar);
            az = fma2(wz[2 * i],     hv.x, az);
            aa = fma2(wv.x,          hv.x, aa);
            ar = fma2(wr[2 * i + 1], hv.y, ar);
            az = fma2(wz[2 * i + 1], hv.y, az);
            aa = fma2(wv.y,          hv.y, aa);
        }
        float rs  = foldadd(ar);            // ir + hr
        float zs  = foldadd(az);            // iz + hz
        float as_ = foldadd(aa);            // ia + ha

        // n = tanh(ia + r*ha); ha = as_ - ia
        float r = sigm_f(rs);
        float z = sigm_f(zs);
        float n = tanh_f(fmaf(r, as_ - ia, ia));
        h = fmaf(z, h - n, n);              // (1-z)*n + z*h

        if (lane == 0) op[t] = h;
    }
}

extern "C" void kernel_launch(void* const* d_in, const int* in_sizes, int n_in,
                              void* d_out, int out_size) {
    const float* inp    = (const float*)d_in[0];
    const float* wih    = (const float*)d_in[1];
    const float* whh    = (const float*)d_in[2];
    const float* bias   = (const float*)d_in[3];
    const float* bias_n = (const float*)d_in[4];
    float* out = (float*)d_out;

    // 1 batch per warp, 4 warps per CTA -> 512 CTAs, 2048 warps, single wave.
    gru_scan_kernel<<<B_DIM / 4, 128>>>(inp, wih, whh, bias, bias_n, out);
}